// round 1
// baseline (speedup 1.0000x reference)
#include <cuda_runtime.h>

// SeparableConv: x[32,112,112,128] --dw3x3+bias--> y --1x1 (128->256)+bias--> out[32,112,112,256]
// Fused per 8x8 spatial tile. fp32 throughout; GEMM uses packed fma.rn.f32x2.

#define IMG_H 112
#define IMG_W 112
#define CIN   128
#define COUT  256
#define TILE  8          // 8x8 output pixels per block
#define HALO  10         // TILE + 2

// smem layout (floats):
//  [0,      12800)  xs: 10*10*128 halo tile   (reused as Wt[32][256]=8192 in GEMM phase)
//  [12800,  21056)  ys: 64 * 129 (padded)
//  [21056,  22208)  kw: 9*128 depthwise weights
//  [22208,  22336)  kb: 128 depthwise bias
#define SM_XS   0
#define SM_YS   12800
#define SM_KW   21056
#define SM_KB   22208
#define SM_FLOATS 22336
#define SM_BYTES  (SM_FLOATS * 4)

__device__ __forceinline__ unsigned long long pack2(float a) {
    unsigned long long r;
    asm("mov.b64 %0, {%1, %1};" : "=l"(r) : "f"(a));
    return r;
}
__device__ __forceinline__ unsigned long long fma2(unsigned long long a,
                                                   unsigned long long b,
                                                   unsigned long long c) {
    unsigned long long d;
    asm("fma.rn.f32x2 %0, %1, %2, %3;" : "=l"(d) : "l"(a), "l"(b), "l"(c));
    return d;
}
__device__ __forceinline__ float2 unpack2(unsigned long long v) {
    float2 f;
    asm("mov.b64 {%0, %1}, %2;" : "=f"(f.x), "=f"(f.y) : "l"(v));
    return f;
}

extern __shared__ float smem[];

__global__ __launch_bounds__(256, 2)
void sepconv_fused_kernel(const float* __restrict__ x,
                          const float* __restrict__ dwk,   // [3][3][1][128]
                          const float* __restrict__ dwb,   // [128]
                          const float* __restrict__ pwk,   // [128][256]
                          const float* __restrict__ pwb,   // [256]
                          float* __restrict__ out) {
    const int tid = threadIdx.x;
    const int tx0 = blockIdx.x * TILE;
    const int ty0 = blockIdx.y * TILE;
    const int n   = blockIdx.z;

    float* xs = smem + SM_XS;
    float* ys = smem + SM_YS;
    float* kw = smem + SM_KW;
    float* kb = smem + SM_KB;

    // ---- load depthwise weights/bias into smem ----
    for (int i = tid; i < 9 * CIN; i += 256) kw[i] = dwk[i];
    if (tid < CIN) kb[tid] = dwb[tid];

    // ---- load 10x10x128 halo tile into smem (zero-pad SAME borders) ----
    {
        const float* xn = x + (size_t)n * IMG_H * IMG_W * CIN;
        for (int i = tid; i < HALO * HALO * (CIN / 4); i += 256) {
            int iy = i / (HALO * (CIN / 4));
            int r  = i - iy * (HALO * (CIN / 4));
            int ix = r >> 5;          // / 32
            int cg = r & 31;          // float4 group
            int gy = ty0 - 1 + iy;
            int gx = tx0 - 1 + ix;
            float4 v = make_float4(0.f, 0.f, 0.f, 0.f);
            if ((unsigned)gy < IMG_H && (unsigned)gx < IMG_W)
                v = *(const float4*)(xn + ((size_t)(gy * IMG_W + gx)) * CIN + cg * 4);
            *(float4*)(xs + (iy * HALO + ix) * CIN + cg * 4) = v;
        }
    }
    __syncthreads();

    // ---- depthwise 3x3: lane owns one channel (conflict-free xs reads & ys writes) ----
    {
        const int c = tid & (CIN - 1);
        const float w0 = kw[0 * CIN + c], w1 = kw[1 * CIN + c], w2 = kw[2 * CIN + c];
        const float w3 = kw[3 * CIN + c], w4 = kw[4 * CIN + c], w5 = kw[5 * CIN + c];
        const float w6 = kw[6 * CIN + c], w7 = kw[7 * CIN + c], w8 = kw[8 * CIN + c];
        const float bb = kb[c];
        #pragma unroll 4
        for (int p = (tid >> 7); p < 64; p += 2) {
            int py = p >> 3, px = p & 7;
            const float* xp = xs + (py * HALO + px) * CIN + c;  // top-left tap
            float acc = bb;
            acc += xp[0 * CIN]  * w0 + xp[1 * CIN]  * w1 + xp[2 * CIN]  * w2;
            acc += xp[10 * CIN] * w3 + xp[11 * CIN] * w4 + xp[12 * CIN] * w5;
            acc += xp[20 * CIN] * w6 + xp[21 * CIN] * w7 + xp[22 * CIN] * w8;
            ys[p * 129 + c] = acc;
        }
    }
    __syncthreads();

    // ---- GEMM: out[64 px][256 oc] = ys[64][128] * W[128][256], packed f32x2 ----
    const int lx  = tid & 7;   // pixel lane: pixels lx, lx+8, ..., lx+56  (py = i, px = lx)
    const int tg  = tid >> 3;  // oc group
    const int oc0 = tg * 8;

    unsigned long long acc[8][4];
    {
        const unsigned long long* pb = (const unsigned long long*)(pwb + oc0);
        unsigned long long b0 = pb[0], b1 = pb[1], b2 = pb[2], b3 = pb[3];
        #pragma unroll
        for (int i = 0; i < 8; i++) {
            acc[i][0] = b0; acc[i][1] = b1; acc[i][2] = b2; acc[i][3] = b3;
        }
    }

    float* Wt = smem + SM_XS;  // reuse xs region: 32*256 floats
    for (int kc = 0; kc < CIN; kc += 32) {
        __syncthreads();  // previous chunk (or depthwise xs use) done
        for (int i = tid; i < 32 * (COUT / 4); i += 256) {
            int rr = i >> 6;
            int c4 = i & 63;
            *(float4*)(Wt + rr * COUT + c4 * 4) =
                *(const float4*)(pwk + (size_t)(kc + rr) * COUT + c4 * 4);
        }
        __syncthreads();

        #pragma unroll 8
        for (int k = 0; k < 32; k++) {
            const unsigned long long* brow =
                (const unsigned long long*)(Wt + k * COUT + oc0);
            unsigned long long b0 = brow[0], b1 = brow[1], b2 = brow[2], b3 = brow[3];
            const float* ycol = ys + lx * 129 + (kc + k);
            #pragma unroll
            for (int i = 0; i < 8; i++) {
                unsigned long long a2 = pack2(ycol[i * 8 * 129]);
                acc[i][0] = fma2(a2, b0, acc[i][0]);
                acc[i][1] = fma2(a2, b1, acc[i][1]);
                acc[i][2] = fma2(a2, b2, acc[i][2]);
                acc[i][3] = fma2(a2, b3, acc[i][3]);
            }
        }
    }

    // ---- epilogue: pixel (ty0+i, tx0+lx), oc0..oc0+7 ----
    #pragma unroll
    for (int i = 0; i < 8; i++) {
        size_t row = ((size_t)(n * IMG_H + ty0 + i) * IMG_W + (tx0 + lx));
        float* op = out + row * COUT + oc0;
        float2 f0 = unpack2(acc[i][0]);
        float2 f1 = unpack2(acc[i][1]);
        float2 f2 = unpack2(acc[i][2]);
        float2 f3 = unpack2(acc[i][3]);
        float4 v0 = make_float4(f0.x, f0.y, f1.x, f1.y);
        float4 v1 = make_float4(f2.x, f2.y, f3.x, f3.y);
        *(float4*)op       = v0;
        *(float4*)(op + 4) = v1;
    }
}

extern "C" void kernel_launch(void* const* d_in, const int* in_sizes, int n_in,
                              void* d_out, int out_size) {
    const float* x   = (const float*)d_in[0];
    const float* dwk = (const float*)d_in[1];
    const float* dwb = (const float*)d_in[2];
    const float* pwk = (const float*)d_in[3];
    const float* pwb = (const float*)d_in[4];
    float* out = (float*)d_out;

    static bool attr_set = false;
    if (!attr_set) {
        cudaFuncSetAttribute(sepconv_fused_kernel,
                             cudaFuncAttributeMaxDynamicSharedMemorySize, SM_BYTES);
        attr_set = true;
    }

    dim3 grid(IMG_W / TILE, IMG_H / TILE, 32);
    sepconv_fused_kernel<<<grid, 256, SM_BYTES>>>(x, dwk, dwb, pwk, pwb, out);
}

// round 3
// speedup vs baseline: 4.1951x; 4.1951x over previous
#include <cuda_runtime.h>
#include <cuda_fp16.h>
#include <cstdint>

// SeparableConv fused: per 8x8-pixel tile
//   cp.async halo(10x10x128 fp32) -> depthwise 3x3+bias -> fp16 split (hi,lo)
//   -> mma.sync m16n8k16 (f16 in, f32 accum): out = yh*W + yl*W, W fp16
// Persistent grid of 148 CTAs x 256 threads. W resident in smem.

#define IMG_H 112
#define IMG_W 112
#define CIN   128
#define COUT  256
#define NIMG  32
#define TILES_X 14
#define TILES_Y 14
#define NTILES (NIMG * TILES_X * TILES_Y)   // 6272
#define GRID  148

// ---- smem layout (bytes) ----
// B   [256][136] fp16                      0      .. 69632
// bias[256] f32                            69632  .. 70656
// kw  [9][128] f32                         70656  .. 75264
// kb  [128] f32                            75264  .. 75776
// xs  10*10*128 f32 (halo)                 75776  .. 126976
// A   [2][64][136] fp16 (yh, yl)           126976 .. 161792
// ys  [64][132] f32                        161792 .. 195584
#define SM_B    0
#define SM_BIAS 69632
#define SM_KW   70656
#define SM_KB   75264
#define SM_XS   75776
#define SM_A    126976
#define SM_YS   161792
#define SM_BYTES 195584

#define A_ROW_B   272          // 136 fp16
#define A_SPLIT_B 17408        // 64 * 272
#define B_ROW_B   272

extern __shared__ unsigned char smem[];

__device__ __forceinline__ uint32_t smem_u32(const void* p) {
    uint32_t a;
    asm("{ .reg .u64 t; cvta.to.shared.u64 t, %1; cvt.u32.u64 %0, t; }" : "=r"(a) : "l"(p));
    return a;
}
__device__ __forceinline__ void ldsm_x4(uint32_t* r, uint32_t addr) {
    asm volatile("ldmatrix.sync.aligned.m8n8.x4.shared.b16 {%0,%1,%2,%3}, [%4];"
                 : "=r"(r[0]), "=r"(r[1]), "=r"(r[2]), "=r"(r[3]) : "r"(addr));
}
__device__ __forceinline__ void mma16816(float* d, const uint32_t* a,
                                         const uint32_t* b, const float* c) {
    asm volatile(
        "mma.sync.aligned.m16n8k16.row.col.f32.f16.f16.f32 "
        "{%0,%1,%2,%3}, {%4,%5,%6,%7}, {%8,%9}, {%10,%11,%12,%13};"
        : "=f"(d[0]), "=f"(d[1]), "=f"(d[2]), "=f"(d[3])
        : "r"(a[0]), "r"(a[1]), "r"(a[2]), "r"(a[3]),
          "r"(b[0]), "r"(b[1]),
          "f"(c[0]), "f"(c[1]), "f"(c[2]), "f"(c[3]));
}
__device__ __forceinline__ void cp16(uint32_t dst, const void* src, int sz) {
    asm volatile("cp.async.cg.shared.global [%0], [%1], 16, %2;"
                 :: "r"(dst), "l"(src), "r"(sz) : "memory");
}
#define CP_COMMIT() asm volatile("cp.async.commit_group;" ::: "memory")
#define CP_WAIT0()  asm volatile("cp.async.wait_group 0;" ::: "memory")

__device__ __forceinline__ void prefetch_halo(const float* __restrict__ x,
                                              uint32_t xs_addr, int t, int tid) {
    int n   = t / (TILES_X * TILES_Y);
    int rem = t - n * (TILES_X * TILES_Y);
    int by  = rem / TILES_X;
    int bx  = rem - by * TILES_X;
    int ty0 = by * 8 - 1, tx0 = bx * 8 - 1;
    const float* xn = x + (size_t)n * (IMG_H * IMG_W * CIN);
    for (int i = tid; i < 3200; i += 256) {
        int iy = i / 320;
        int r  = i - iy * 320;
        int ix = r >> 5;
        int cg = r & 31;
        int gy = ty0 + iy, gx = tx0 + ix;
        bool ok = ((unsigned)gy < IMG_H) && ((unsigned)gx < IMG_W);
        const float* src = ok ? (xn + ((size_t)(gy * IMG_W + gx)) * CIN + cg * 4) : xn;
        int sz = ok ? 16 : 0;
        uint32_t dst = xs_addr + (uint32_t)(((iy * 10 + ix) * CIN + cg * 4) * 4);
        cp16(dst, src, sz);
    }
    CP_COMMIT();
}

__device__ __forceinline__ uint32_t pack_h2(__half a, __half b) {
    __half2 h = __halves2half2(a, b);
    return *reinterpret_cast<uint32_t*>(&h);
}

__global__ __launch_bounds__(256, 1)
void sepconv_mma_kernel(const float* __restrict__ x,
                        const float* __restrict__ dwk,
                        const float* __restrict__ dwb,
                        const float* __restrict__ pwk,
                        const float* __restrict__ pwb,
                        float* __restrict__ out) {
    const int tid  = threadIdx.x;
    const int lane = tid & 31;
    const int wid  = tid >> 5;

    const uint32_t s0    = smem_u32(smem);
    const uint32_t xs_a  = s0 + SM_XS;
    const uint32_t A_a   = s0 + SM_A;
    const uint32_t B_a   = s0 + SM_B;

    float* xs   = (float*)(smem + SM_XS);
    float* ys   = (float*)(smem + SM_YS);
    float* kw   = (float*)(smem + SM_KW);
    float* kb   = (float*)(smem + SM_KB);
    float* bias = (float*)(smem + SM_BIAS);
    __half* Bs  = (__half*)(smem + SM_B);

    // ---- prologue: dw weights, bias, W(fp16, [n][k] padded 136) ----
    for (int i = tid; i < 9 * CIN; i += 256) kw[i] = dwk[i];
    if (tid < CIN) kb[tid] = dwb[tid];
    for (int i = tid; i < COUT; i += 256) bias[i] = pwb[i];
    for (int i = tid; i < CIN * COUT; i += 256) {
        int k = i >> 8;      // 0..127
        int n = i & 255;     // 0..255
        Bs[n * 136 + k] = __float2half_rn(pwk[i]);
    }
    // first halo prefetch
    int t0 = blockIdx.x;
    if (t0 < NTILES) prefetch_halo(x, xs_a, t0, tid);
    __syncthreads();

    // hoisted per-thread constants
    const int c = tid & (CIN - 1);
    const float w0 = kw[0*CIN+c], w1 = kw[1*CIN+c], w2 = kw[2*CIN+c];
    const float w3 = kw[3*CIN+c], w4 = kw[4*CIN+c], w5 = kw[5*CIN+c];
    const float w6 = kw[6*CIN+c], w7 = kw[7*CIN+c], w8 = kw[8*CIN+c];
    const float bb = kb[c];

    // warp tiling: 8 warps as 2 (M) x 4 (N); warp tile 32 x 64
    const int wm = wid >> 2;          // 0..1
    const int wn = wid & 3;           // 0..3
    const int m0 = wm * 32;
    const int n0 = wn * 64;

    // per-lane ldmatrix base addresses
    const uint32_t addrA0 = A_a + (uint32_t)(m0 + (lane & 15)) * A_ROW_B + (lane & 16);
    const uint32_t addrB0 = B_a + (uint32_t)(n0 + (lane & 7) + ((lane & 16) >> 1)) * B_ROW_B
                                + ((lane & 8) << 1);

    // bias pairs per lane (cols n0 + nj*8 + (lane&3)*2)
    float2 bini[8];
    #pragma unroll
    for (int nj = 0; nj < 8; nj++) {
        int col = n0 + nj * 8 + (lane & 3) * 2;
        bini[nj].x = bias[col];
        bini[nj].y = bias[col + 1];
    }

    for (int t = blockIdx.x; t < NTILES; t += GRID) {
        // decompose tile
        int n   = t / (TILES_X * TILES_Y);
        int rem = t - n * (TILES_X * TILES_Y);
        int by  = rem / TILES_X;
        int bx  = rem - by * TILES_X;
        int ty0 = by * 8, tx0 = bx * 8;

        CP_WAIT0();
        __syncthreads();            // halo(t) resident in xs

        // ---- depthwise 3x3 ----
        #pragma unroll 4
        for (int p = (tid >> 7); p < 64; p += 2) {
            int py = p >> 3, px = p & 7;
            const float* xp = xs + (py * 10 + px) * CIN + c;
            float acc = bb;
            acc += xp[0*CIN]  * w0 + xp[1*CIN]  * w1 + xp[2*CIN]  * w2;
            acc += xp[10*CIN] * w3 + xp[11*CIN] * w4 + xp[12*CIN] * w5;
            acc += xp[20*CIN] * w6 + xp[21*CIN] * w7 + xp[22*CIN] * w8;
            ys[p * 132 + c] = acc;
        }
        __syncthreads();            // ys ready; halo dead

        // prefetch next tile's halo (overlaps convert + mma + epilogue)
        int tn = t + GRID;
        if (tn < NTILES) prefetch_halo(x, xs_a, tn, tid);

        // ---- fp16 split: ys -> A[0]=hi, A[1]=lo ----
        #pragma unroll
        for (int j = 0; j < 4; j++) {
            int idx = tid + 256 * j;       // 0..1023
            int p  = idx >> 4;             // pixel 0..63
            int kg = idx & 15;             // 8-ch group
            const float* yp = ys + p * 132 + kg * 8;
            float4 a4 = *(const float4*)yp;
            float4 b4 = *(const float4*)(yp + 4);
            float v[8] = {a4.x, a4.y, a4.z, a4.w, b4.x, b4.y, b4.z, b4.w};
            uint32_t hi[4], lo[4];
            #pragma unroll
            for (int q = 0; q < 4; q++) {
                __half h0 = __float2half_rn(v[2*q]);
                __half h1 = __float2half_rn(v[2*q+1]);
                __half l0 = __float2half_rn(v[2*q]   - __half2float(h0));
                __half l1 = __float2half_rn(v[2*q+1] - __half2float(h1));
                hi[q] = pack_h2(h0, h1);
                lo[q] = pack_h2(l0, l1);
            }
            uint32_t off = (uint32_t)p * A_ROW_B + (uint32_t)kg * 16;
            *(uint4*)(smem + SM_A + off)             = make_uint4(hi[0], hi[1], hi[2], hi[3]);
            *(uint4*)(smem + SM_A + A_SPLIT_B + off) = make_uint4(lo[0], lo[1], lo[2], lo[3]);
        }
        __syncthreads();            // A ready

        // ---- MMA: acc[2 mi][8 nj][4] ----
        float acc[2][8][4];
        #pragma unroll
        for (int mi = 0; mi < 2; mi++)
            #pragma unroll
            for (int nj = 0; nj < 8; nj++) {
                acc[mi][nj][0] = bini[nj].x; acc[mi][nj][1] = bini[nj].y;
                acc[mi][nj][2] = bini[nj].x; acc[mi][nj][3] = bini[nj].y;
            }

        #pragma unroll 2
        for (int ks = 0; ks < 16; ks++) {
            int split = ks >> 3;
            int kk    = ks & 7;
            uint32_t aA = addrA0 + (uint32_t)split * A_SPLIT_B + (uint32_t)kk * 32;
            uint32_t aB = addrB0 + (uint32_t)kk * 32;
            uint32_t afr[2][4];
            ldsm_x4(afr[0], aA);
            ldsm_x4(afr[1], aA + 16 * A_ROW_B);
            uint32_t bfr[4][4];
            #pragma unroll
            for (int j = 0; j < 4; j++) ldsm_x4(bfr[j], aB + (uint32_t)j * 16 * B_ROW_B);
            #pragma unroll
            for (int j = 0; j < 4; j++) {
                mma16816(acc[0][2*j],   afr[0], &bfr[j][0], acc[0][2*j]);
                mma16816(acc[0][2*j+1], afr[0], &bfr[j][2], acc[0][2*j+1]);
                mma16816(acc[1][2*j],   afr[1], &bfr[j][0], acc[1][2*j]);
                mma16816(acc[1][2*j+1], afr[1], &bfr[j][2], acc[1][2*j+1]);
            }
        }

        // ---- epilogue ----
        #pragma unroll
        for (int mi = 0; mi < 2; mi++) {
            int r0 = m0 + mi * 16 + (lane >> 2);
            int r1 = r0 + 8;
            float* o0 = out + ((size_t)((n * IMG_H + ty0 + (r0 >> 3)) * IMG_W)
                               + tx0 + (r0 & 7)) * COUT;
            float* o1 = out + ((size_t)((n * IMG_H + ty0 + (r1 >> 3)) * IMG_W)
                               + tx0 + (r1 & 7)) * COUT;
            #pragma unroll
            for (int nj = 0; nj < 8; nj++) {
                int col = n0 + nj * 8 + (lane & 3) * 2;
                *(float2*)(o0 + col) = make_float2(acc[mi][nj][0], acc[mi][nj][1]);
                *(float2*)(o1 + col) = make_float2(acc[mi][nj][2], acc[mi][nj][3]);
            }
        }
        __syncthreads();            // all reads of A/ys done before next overwrite
    }
}

extern "C" void kernel_launch(void* const* d_in, const int* in_sizes, int n_in,
                              void* d_out, int out_size) {
    const float* x   = (const float*)d_in[0];
    const float* dwk = (const float*)d_in[1];
    const float* dwb = (const float*)d_in[2];
    const float* pwk = (const float*)d_in[3];
    const float* pwb = (const float*)d_in[4];
    float* out = (float*)d_out;

    static bool init = false;
    if (!init) {
        cudaFuncSetAttribute(sepconv_mma_kernel,
                             cudaFuncAttributeMaxDynamicSharedMemorySize, SM_BYTES);
        init = true;
    }
    sepconv_mma_kernel<<<GRID, 256, SM_BYTES>>>(x, dwk, dwb, pwk, pwb, out);
}

// round 4
// speedup vs baseline: 4.6021x; 1.0970x over previous
#include <cuda_runtime.h>
#include <cuda_fp16.h>
#include <cstdint>

// SeparableConv fused, round 4:
//  - depthwise 3x3 from GLOBAL via registers (no xs/ys smem), fp16 hi/lo split in regs
//  - A[2][64][136]f16 + B[256][136]f16 resident in smem (103KB -> 2 CTAs/SM)
//  - mma.sync m16n8k16, B frags reused across hi/lo splits
//  - B column-permuted so epilogue is contiguous float4 stores

#define IMG_H 112
#define IMG_W 112
#define CIN   128
#define COUT  256
#define NIMG  32
#define TILES_X 14
#define TILES_Y 14
#define NTILES (NIMG * TILES_X * TILES_Y)   // 6272
#define GRID  296

// smem (bytes): B[256][136]f16 = 69632 | bias 1024 | A[2][64][136]f16 = 34816
#define SM_B    0
#define SM_BIAS 69632
#define SM_A    70656
#define SM_BYTES 105472

#define A_ROW_B   272
#define A_SPLIT_B 17408        // 64*272
#define B_ROW_B   272

extern __shared__ unsigned char smem[];

__device__ __forceinline__ uint32_t smem_u32(const void* p) {
    uint32_t a;
    asm("{ .reg .u64 t; cvta.to.shared.u64 t, %1; cvt.u32.u64 %0, t; }" : "=r"(a) : "l"(p));
    return a;
}
__device__ __forceinline__ void ldsm_x4(uint32_t* r, uint32_t addr) {
    asm volatile("ldmatrix.sync.aligned.m8n8.x4.shared.b16 {%0,%1,%2,%3}, [%4];"
                 : "=r"(r[0]), "=r"(r[1]), "=r"(r[2]), "=r"(r[3]) : "r"(addr));
}
__device__ __forceinline__ void mma16816(float* d, const uint32_t* a,
                                         const uint32_t* b, const float* c) {
    asm volatile(
        "mma.sync.aligned.m16n8k16.row.col.f32.f16.f16.f32 "
        "{%0,%1,%2,%3}, {%4,%5,%6,%7}, {%8,%9}, {%10,%11,%12,%13};"
        : "=f"(d[0]), "=f"(d[1]), "=f"(d[2]), "=f"(d[3])
        : "r"(a[0]), "r"(a[1]), "r"(a[2]), "r"(a[3]),
          "r"(b[0]), "r"(b[1]),
          "f"(c[0]), "f"(c[1]), "f"(c[2]), "f"(c[3]));
}

__global__ __launch_bounds__(256, 2)
void sepconv_mma_kernel(const float* __restrict__ x,
                        const float* __restrict__ dwk,
                        const float* __restrict__ dwb,
                        const float* __restrict__ pwk,
                        const float* __restrict__ pwb,
                        float* __restrict__ out) {
    const int tid  = threadIdx.x;
    const int lane = tid & 31;
    const int wid  = tid >> 5;

    const uint32_t s0  = smem_u32(smem);
    const uint32_t A_a = s0 + SM_A;
    const uint32_t B_a = s0 + SM_B;

    __half* Bs   = (__half*)(smem + SM_B);
    float*  bias = (float*)(smem + SM_BIAS);
    unsigned char* Asm = smem + SM_A;

    // ---- prologue: bias + permuted B(fp16) ----
    for (int i = tid; i < COUT; i += 256) bias[i] = pwb[i];
    for (int i = tid; i < CIN * COUT; i += 256) {
        int k = i >> 8;         // in-channel
        int n = i & 255;        // physical out col
        int seg = n & 192;      // 64-col warp segment
        int q   = n & 63;
        // frag (nj,c8) <- physical p = g*16 + nj*2 + b ; smem row = seg + nj*8 + g*2 + b
        int row = seg + ((q & 15) >> 1) * 8 + (q >> 4) * 2 + (q & 1);
        Bs[row * 136 + k] = __float2half_rn(pwk[k * 256 + n]);
    }

    // depthwise weights in registers (channel c, column-half h)
    const int c = tid & 127;
    const int h = tid >> 7;
    float w[9];
    #pragma unroll
    for (int t = 0; t < 9; t++) w[t] = dwk[t * CIN + c];
    const float bb = dwb[c];
    __syncthreads();

    // warp tiling: 2 (M) x 4 (N), warp tile 32 x 64
    const int wm = wid >> 2, wn = wid & 3;
    const int m0 = wm * 32;
    const int n0 = wn * 64;
    const int g  = lane & 3;
    const int rr = lane >> 2;

    const uint32_t addrA0 = A_a + (uint32_t)(m0 + (lane & 15)) * A_ROW_B + (lane & 16);
    const uint32_t addrB0 = B_a + (uint32_t)(n0 + (lane & 7) + ((lane & 16) >> 1)) * B_ROW_B
                                + ((lane & 8) << 1);

    const uint32_t aoff_c = (uint32_t)c * 2;   // channel byte offset in A row

    for (int t = blockIdx.x; t < NTILES; t += GRID) {
        int n   = t / (TILES_X * TILES_Y);
        int rem = t - n * (TILES_X * TILES_Y);
        int by  = rem / TILES_X;
        int bx  = rem - by * TILES_X;
        int ty0 = by * 8, tx0 = bx * 8;

        // ================= depthwise (registers, global loads) =================
        uint32_t hi2[16], lo2[16];   // [(px_h)*4 + pys] = halves (py even, py odd)
        const float* xn = x + (size_t)n * (IMG_H * IMG_W * CIN) + c;

        #pragma unroll
        for (int pxp = 0; pxp < 2; pxp++) {
            float xv[4][10];
            int gx0 = tx0 + 4 * h + 2 * pxp - 1;
            #pragma unroll
            for (int j = 0; j < 4; j++) {
                int gx = gx0 + j;
                bool okx = (unsigned)gx < IMG_W;
                #pragma unroll
                for (int r = 0; r < 10; r++) {
                    int gy = ty0 - 1 + r;
                    bool ok = okx && ((unsigned)gy < IMG_H);
                    xv[j][r] = ok ? xn[((size_t)gy * IMG_W + gx) * CIN] : 0.0f;
                }
            }
            #pragma unroll
            for (int e = 0; e < 2; e++) {
                #pragma unroll
                for (int pys = 0; pys < 4; pys++) {
                    float y0 = bb, y1 = bb;
                    #pragma unroll
                    for (int di = 0; di < 3; di++)
                        #pragma unroll
                        for (int dj = 0; dj < 3; dj++) {
                            float ww = w[di * 3 + dj];
                            y0 += xv[e + dj][2 * pys + di]     * ww;
                            y1 += xv[e + dj][2 * pys + 1 + di] * ww;
                        }
                    __half2 hy = __floats2half2_rn(y0, y1);
                    float r0 = y0 - __low2float(hy);
                    float r1 = y1 - __high2float(hy);
                    __half2 ly = __floats2half2_rn(r0, r1);
                    int idx = (pxp * 2 + e) * 4 + pys;
                    hi2[idx] = *reinterpret_cast<uint32_t*>(&hy);
                    lo2[idx] = *reinterpret_cast<uint32_t*>(&ly);
                }
            }
        }

        __syncthreads();   // all warps done reading A of previous tile

        // store A: pixel p = py*8 + px_g, fp16 at A[split][p][c]
        #pragma unroll
        for (int v = 0; v < 16; v++) {
            int px_h = v >> 2, pys = v & 3;
            int p0 = (2 * pys) * 8 + (4 * h + px_h);
            uint32_t off = (uint32_t)p0 * A_ROW_B + aoff_c;
            *(uint16_t*)(Asm + off)                      = (uint16_t)hi2[v];
            *(uint16_t*)(Asm + off + 8 * A_ROW_B)        = (uint16_t)(hi2[v] >> 16);
            *(uint16_t*)(Asm + A_SPLIT_B + off)          = (uint16_t)lo2[v];
            *(uint16_t*)(Asm + A_SPLIT_B + off + 8 * A_ROW_B) = (uint16_t)(lo2[v] >> 16);
        }
        __syncthreads();   // A ready

        // ================= MMA =================
        float acc[2][8][4];
        #pragma unroll
        for (int mi = 0; mi < 2; mi++)
            #pragma unroll
            for (int nj = 0; nj < 8; nj++)
                #pragma unroll
                for (int q = 0; q < 4; q++) acc[mi][nj][q] = 0.0f;

        #pragma unroll
        for (int kk = 0; kk < 8; kk++) {
            uint32_t aB = addrB0 + (uint32_t)kk * 32;
            uint32_t bfr[4][4];
            #pragma unroll
            for (int j = 0; j < 4; j++) ldsm_x4(bfr[j], aB + (uint32_t)j * 16 * B_ROW_B);
            #pragma unroll
            for (int s = 0; s < 2; s++) {
                uint32_t aA = addrA0 + (uint32_t)s * A_SPLIT_B + (uint32_t)kk * 32;
                uint32_t afr[2][4];
                ldsm_x4(afr[0], aA);
                ldsm_x4(afr[1], aA + 16 * A_ROW_B);
                #pragma unroll
                for (int j = 0; j < 4; j++) {
                    mma16816(acc[0][2*j],   afr[0], &bfr[j][0], acc[0][2*j]);
                    mma16816(acc[0][2*j+1], afr[0], &bfr[j][2], acc[0][2*j+1]);
                    mma16816(acc[1][2*j],   afr[1], &bfr[j][0], acc[1][2*j]);
                    mma16816(acc[1][2*j+1], afr[1], &bfr[j][2], acc[1][2*j+1]);
                }
            }
        }

        // ================= epilogue (contiguous float4, permuted cols) =========
        #pragma unroll
        for (int mi = 0; mi < 2; mi++) {
            int r0 = m0 + mi * 16 + rr;
            int r1 = r0 + 8;
            float* o0 = out + ((size_t)((n * IMG_H + ty0 + (r0 >> 3)) * IMG_W)
                               + tx0 + (r0 & 7)) * COUT + n0 + g * 16;
            float* o1 = out + ((size_t)((n * IMG_H + ty0 + (r1 >> 3)) * IMG_W)
                               + tx0 + (r1 & 7)) * COUT + n0 + g * 16;
            #pragma unroll
            for (int k = 0; k < 4; k++) {
                float4 b4 = *(const float4*)(bias + n0 + g * 16 + k * 4);
                float4 v0, v1;
                v0.x = acc[mi][2*k][0]   + b4.x;
                v0.y = acc[mi][2*k][1]   + b4.y;
                v0.z = acc[mi][2*k+1][0] + b4.z;
                v0.w = acc[mi][2*k+1][1] + b4.w;
                v1.x = acc[mi][2*k][2]   + b4.x;
                v1.y = acc[mi][2*k][3]   + b4.y;
                v1.z = acc[mi][2*k+1][2] + b4.z;
                v1.w = acc[mi][2*k+1][3] + b4.w;
                *(float4*)(o0 + k * 4) = v0;
                *(float4*)(o1 + k * 4) = v1;
            }
        }
    }
}

extern "C" void kernel_launch(void* const* d_in, const int* in_sizes, int n_in,
                              void* d_out, int out_size) {
    const float* x   = (const float*)d_in[0];
    const float* dwk = (const float*)d_in[1];
    const float* dwb = (const float*)d_in[2];
    const float* pwk = (const float*)d_in[3];
    const float* pwb = (const float*)d_in[4];
    float* out = (float*)d_out;

    static bool init = false;
    if (!init) {
        cudaFuncSetAttribute(sepconv_mma_kernel,
                             cudaFuncAttributeMaxDynamicSharedMemorySize, SM_BYTES);
        init = true;
    }
    sepconv_mma_kernel<<<GRID, 256, SM_BYTES>>>(x, dwk, dwb, pwk, pwb, out);
}